// round 5
// baseline (speedup 1.0000x reference)
#include <cuda_runtime.h>
#include <math.h>

// ---------------------------------------------------------------------------
// SimplifiedIFEBranch — R5: persistent kernel, 2-D tiled FC (A staged in smem,
// K-split with smem reduction + one global atomicAdd per partial), FFMA2,
// bias pre-init + W1 prefetch overlapped with histogram phase.
// ---------------------------------------------------------------------------

#define NBINS 32
#define NCTA  128
#define SMEM_FLOATS 24576                  // 96 KB dynamic smem
#define SMEM_BYTES  (SMEM_FLOATS * 4)

__device__ __forceinline__ float c_LO() { return (float)(-3.2 - (6.4 / 256.0) / 2.0); }
__device__ __forceinline__ float c_HI() { return (float)( 3.2 - (6.4 / 256.0) / 2.0); }
__device__ __forceinline__ float c_BW() {
    return (float)(((3.2 - (6.4 / 256.0) / 2.0) - (-3.2 - (6.4 / 256.0) / 2.0)) / 32.0);
}

// Scratch + barrier state (__device__ globals; no allocation allowed)
__device__ float g_histT[3072 * 32];      // normalized, transposed [k][b]
__device__ float g_x1T[1024 * 32];        // pre-relu accumulators (bias-inited)
__device__ float g_x2T[512 * 32];
__device__ unsigned int g_bar_count = 0;
__device__ unsigned int g_bar_gen   = 0;

// ---- packed f32x2 helpers ---------------------------------------------------
__device__ __forceinline__ unsigned long long pack2(float x, float y) {
    unsigned long long r;
    asm("mov.b64 %0, {%1, %2};" : "=l"(r) : "f"(x), "f"(y));
    return r;
}
__device__ __forceinline__ void ffma2(unsigned long long& d,
                                      unsigned long long a, unsigned long long b) {
    asm("fma.rn.f32x2 %0, %1, %2, %0;" : "+l"(d) : "l"(a), "l"(b));
}
__device__ __forceinline__ float unpack_sum(unsigned long long p) {
    float lo, hi;
    asm("mov.b64 {%0, %1}, %2;" : "=f"(lo), "=f"(hi) : "l"(p));
    return lo + hi;
}

// ---- software grid barrier (all NCTA CTAs resident) -------------------------
__device__ __forceinline__ void grid_barrier() {
    __syncthreads();
    if (threadIdx.x == 0) {
        unsigned gen = *(volatile unsigned*)&g_bar_gen;
        __threadfence();
        unsigned old = atomicAdd(&g_bar_count, 1u);
        if (old == NCTA - 1) {
            g_bar_count = 0;
            __threadfence();
            atomicAdd(&g_bar_gen, 1u);
        } else {
            while (*(volatile unsigned*)&g_bar_gen == gen) { __nanosleep(32); }
        }
        __threadfence();
    }
    __syncthreads();
}

// ---- histogram helper --------------------------------------------------------
__device__ __forceinline__ void hist_add(float* h, float Iu, float Iv, float w) {
    const float LO = c_LO(), HI = c_HI(), BW = c_BW();
    if (Iu >= LO && Iu <= HI && Iv >= LO && Iv <= HI) {
        int iu = (int)floorf((Iu - LO) / BW);
        int iv = (int)floorf((Iv - LO) / BW);
        iu = min(max(iu, 0), NBINS - 1);
        iv = min(max(iv, 0), NBINS - 1);
        atomicAdd(&h[iu * NBINS + iv], w);
    }
}

// ---- tiled FC phase ----------------------------------------------------------
// CTA tile: NT_CTA = NG*NT neurons x KS of K. Warps: NG n-groups x KG k-groups.
// A slice [KS,32] staged in smem (optional relu on fill). K-split partials
// reduced in smem, then ONE atomicAdd per (n,b) per CTA into accum (bias-inited).
template <int KTOT, int KS, int NG, int NT, int KG, bool RELU_IN>
__device__ __forceinline__ void fc_tile(const float* __restrict__ AT,
                                        const float* __restrict__ W,
                                        float* __restrict__ accum,
                                        float* buf, int nb_i, int kb_i) {
    constexpr int CH = KS / KG;
    const int n0   = nb_i * (NG * NT);
    const int K0   = kb_i * KS;
    const int lane = threadIdx.x & 31;
    const int w    = threadIdx.x >> 5;
    const int ng   = w & (NG - 1);
    const int kg   = w / NG;

    // stage A slice (contiguous KS*32 floats), vectorized, optional relu
    {
        const float4* src = reinterpret_cast<const float4*>(AT + (size_t)K0 * 32);
        float4* dst = reinterpret_cast<float4*>(buf);
        #pragma unroll
        for (int i = threadIdx.x; i < KS * 8; i += 1024) {
            float4 v = __ldcg(src + i);
            if (RELU_IN) {
                v.x = fmaxf(v.x, 0.f); v.y = fmaxf(v.y, 0.f);
                v.z = fmaxf(v.z, 0.f); v.w = fmaxf(v.w, 0.f);
            }
            dst[i] = v;
        }
    }
    __syncthreads();

    const float* a = buf + (size_t)(kg * CH) * 32 + lane;
    const float* wbase = W + (size_t)(n0 + ng * NT) * KTOT + K0 + kg * CH;

    unsigned long long acc2[NT];
    #pragma unroll
    for (int t = 0; t < NT; ++t) acc2[t] = 0ull;

    #pragma unroll 4
    for (int k = 0; k < CH; k += 4) {
        float av0 = a[(k + 0) * 32];
        float av1 = a[(k + 1) * 32];
        float av2 = a[(k + 2) * 32];
        float av3 = a[(k + 3) * 32];
        unsigned long long p01 = pack2(av0, av1);
        unsigned long long p23 = pack2(av2, av3);
        #pragma unroll
        for (int t = 0; t < NT; ++t) {
            ulonglong2 wv = __ldcg(reinterpret_cast<const ulonglong2*>(
                wbase + (size_t)t * KTOT + k));
            ffma2(acc2[t], wv.x, p01);
            ffma2(acc2[t], wv.y, p23);
        }
    }
    __syncthreads();   // A-stage dead; reuse buf as reduction scratch

    #pragma unroll
    for (int t = 0; t < NT; ++t)
        buf[(w * NT + t) * 32 + lane] = unpack_sum(acc2[t]);
    __syncthreads();

    if (w < NG) {                 // warp w reduces n-group w
        #pragma unroll
        for (int t = 0; t < NT; ++t) {
            float s = 0.0f;
            #pragma unroll
            for (int j = 0; j < KG; ++j)
                s += buf[((j * NG + w) * NT + t) * 32 + lane];
            atomicAdd(&accum[(n0 + w * NT + t) * 32 + lane], s);
        }
    }
    __syncthreads();
}

// ---- the one kernel -----------------------------------------------------------
__global__ __launch_bounds__(1024, 1) void fused_kernel(
    const float* __restrict__ img,
    const float* __restrict__ W1, const float* __restrict__ b1,
    const float* __restrict__ W2, const float* __restrict__ b2,
    const float* __restrict__ W3, const float* __restrict__ b3,
    float* __restrict__ out,
    float* __restrict__ histT, float* __restrict__ x1T, float* __restrict__ x2T) {

    extern __shared__ float buf[];         // SMEM_FLOATS floats

    const int cta = blockIdx.x;
    const int tid = threadIdx.x;

    // ---------- Phase 0: hist (CTAs 0..31) | bias-init + W1 prefetch ----------
    if (cta < 32) {
        float* sh   = buf;                 // 3072 bins
        float* ssum = buf + 3072;          // 3 sums
        const int b = cta;
        for (int i = tid; i < 3072; i += 1024) sh[i] = 0.0f;
        if (tid < 3) ssum[tid] = 0.0f;
        __syncthreads();

        const int y = tid >> 5, x = tid & 31;
        const float* base = img + (size_t)b * 3 * 262144;
        const int off = (y * 16) * 512 + (x * 16);       // nearest: floor(i*16)

        float r  = base[off];
        float g  = base[262144 + off];
        float bl = base[524288 + off];
        if (r > 0.0f && g > 0.0f && bl > 0.0f) {
            float w  = sqrtf(r * r + g * g + bl * bl);
            float lr = logf(r), lg = logf(g), lb = logf(bl);
            hist_add(&sh[0],    lr - lb, lr - lg, w);
            hist_add(&sh[1024], lg - lb, lg - lr, w);
            hist_add(&sh[2048], lb - lg, lb - lr, w);
        }
        __syncthreads();

        #pragma unroll
        for (int c = 0; c < 3; ++c) {
            float s = sh[c * 1024 + tid];
            #pragma unroll
            for (int o = 16; o > 0; o >>= 1) s += __shfl_down_sync(0xffffffffu, s, o);
            if ((tid & 31) == 0) atomicAdd(&ssum[c], s);
        }
        __syncthreads();

        #pragma unroll
        for (int c = 0; c < 3; ++c) {
            float v = sh[c * 1024 + tid] / ssum[c];
            histT[(c * 1024 + tid) * 32 + b] = sqrtf(v);
        }
    } else {
        // 96 CTAs x 1024 thr: init x1T/x2T with bias, prefetch all of W1 to L2
        const int idx = (cta - 32) * 1024 + tid;          // 0..98303
        if (idx < 32768)       x1T[idx] = __ldcg(b1 + (idx >> 5));
        else if (idx < 49152) { int j = idx - 32768; x2T[j] = __ldcg(b2 + (j >> 5)); }
        const float* p = W1 + (size_t)idx * 32;
        asm volatile("prefetch.global.L2 [%0];" :: "l"(p));
    }

    grid_barrier();

    // ---------- Phase 1: fc1  (1024 x 3072) — 32 nb x 4 kb tiles --------------
    // CTA: 32 neurons x 768 K. Warps: NG=4 (NT=8) x KG=8 (CH=96).
    fc_tile<3072, 768, 4, 8, 8, false>(histT, W1, x1T, buf, cta & 31, cta >> 5);
    grid_barrier();

    // ---------- Phase 2: fc2  (512 x 1024) — 32 nb x 4 kb tiles ---------------
    // CTA: 16 neurons x 256 K. Warps: NG=4 (NT=4) x KG=8 (CH=32). ReLU on stage.
    fc_tile<1024, 256, 4, 4, 8, true>(x1T, W2, x2T, buf, cta & 31, cta >> 5);
    grid_barrier();

    // ---------- Phase 3: fc3  (256 x 512) — full K, NT=2, relu-on-read --------
    {
        const int n0   = cta * 2;
        const int lane = tid & 31;
        const int w    = tid >> 5;                 // = kg, CH=16
        const float* a = x2T + (size_t)(w * 16) * 32 + lane;
        const float* wb = W3 + (size_t)n0 * 512 + w * 16;

        unsigned long long acc2[2] = {0ull, 0ull};
        #pragma unroll
        for (int k = 0; k < 16; k += 4) {
            float av0 = fmaxf(__ldcg(a + (k + 0) * 32), 0.f);
            float av1 = fmaxf(__ldcg(a + (k + 1) * 32), 0.f);
            float av2 = fmaxf(__ldcg(a + (k + 2) * 32), 0.f);
            float av3 = fmaxf(__ldcg(a + (k + 3) * 32), 0.f);
            unsigned long long p01 = pack2(av0, av1);
            unsigned long long p23 = pack2(av2, av3);
            #pragma unroll
            for (int t = 0; t < 2; ++t) {
                ulonglong2 wv = __ldcg(reinterpret_cast<const ulonglong2*>(
                    wb + (size_t)t * 512 + k));
                ffma2(acc2[t], wv.x, p01);
                ffma2(acc2[t], wv.y, p23);
            }
        }
        __syncthreads();
        #pragma unroll
        for (int t = 0; t < 2; ++t)
            buf[(w * 2 + t) * 32 + lane] = unpack_sum(acc2[t]);
        __syncthreads();

        if (w < 2) {               // warp w finishes neuron n0+w
            float s = 0.0f;
            #pragma unroll
            for (int j = 0; j < 32; ++j) s += buf[(j * 2 + w) * 32 + lane];
            s += __ldcg(b3 + n0 + w);
            s = fmaxf(s, 0.0f);
            out[lane * 256 + n0 + w] = s;          // [32][256]
        }
    }
}

extern "C" void kernel_launch(void* const* d_in, const int* in_sizes, int n_in,
                              void* d_out, int out_size) {
    const float* inp = (const float*)d_in[0];
    const float* W1  = (const float*)d_in[1];
    const float* b1  = (const float*)d_in[2];
    const float* W2  = (const float*)d_in[3];
    const float* b2  = (const float*)d_in[4];
    const float* W3  = (const float*)d_in[5];
    const float* b3  = (const float*)d_in[6];
    float* out = (float*)d_out;

    float* histT; cudaGetSymbolAddress((void**)&histT, g_histT);
    float* x1T;   cudaGetSymbolAddress((void**)&x1T,   g_x1T);
    float* x2T;   cudaGetSymbolAddress((void**)&x2T,   g_x2T);

    cudaFuncSetAttribute(fused_kernel,
                         cudaFuncAttributeMaxDynamicSharedMemorySize, SMEM_BYTES);
    fused_kernel<<<NCTA, 1024, SMEM_BYTES>>>(inp, W1, b1, W2, b2, W3, b3, out,
                                             histT, x1T, x2T);
}

// round 6
// speedup vs baseline: 1.2783x; 1.2783x over previous
#include <cuda_runtime.h>
#include <math.h>

// ---------------------------------------------------------------------------
// SimplifiedIFEBranch — R6: persistent kernel (128 CTAs x 512 thr, 128 regs),
// FC with W tile staged in smem (inner loop = LDS.128 + FFMA2 only),
// A operand register-resident (pair-packed u64 loads for fc1), K-split
// partials via bias-preinit + atomicAdd.
// ---------------------------------------------------------------------------

#define NBINS 32
#define NCTA  128
#define SMEM_BYTES (98304 + 256)          // fc1 W tile 96KB + slack

__device__ __forceinline__ float c_LO() { return (float)(-3.2 - (6.4 / 256.0) / 2.0); }
__device__ __forceinline__ float c_HI() { return (float)( 3.2 - (6.4 / 256.0) / 2.0); }
__device__ __forceinline__ float c_BW() {
    return (float)(((3.2 - (6.4 / 256.0) / 2.0) - (-3.2 - (6.4 / 256.0) / 2.0)) / 32.0);
}

// Scratch (__device__ globals; no allocation allowed)
__device__ float g_histP[3072 * 32];   // pair-packed: [(k/2)][b][2] floats
__device__ float g_x1T[1024 * 32];     // [n][b] accum, bias-preinit
__device__ float g_x2T[512 * 32];      // [n][b] accum, bias-preinit
__device__ unsigned int g_bar_count = 0;
__device__ unsigned int g_bar_gen   = 0;

// ---- packed f32x2 helpers ---------------------------------------------------
__device__ __forceinline__ unsigned long long pack2(float x, float y) {
    unsigned long long r;
    asm("mov.b64 %0, {%1, %2};" : "=l"(r) : "f"(x), "f"(y));
    return r;
}
__device__ __forceinline__ void ffma2(unsigned long long& d,
                                      unsigned long long a, unsigned long long b) {
    asm("fma.rn.f32x2 %0, %1, %2, %0;" : "+l"(d) : "l"(a), "l"(b));
}
__device__ __forceinline__ float unpack_sum(unsigned long long p) {
    float lo, hi;
    asm("mov.b64 {%0, %1}, %2;" : "=f"(lo), "=f"(hi) : "l"(p));
    return lo + hi;
}

// ---- software grid barrier (all NCTA CTAs resident) -------------------------
__device__ __forceinline__ void grid_barrier() {
    __syncthreads();
    if (threadIdx.x == 0) {
        unsigned gen = *(volatile unsigned*)&g_bar_gen;
        __threadfence();
        unsigned old = atomicAdd(&g_bar_count, 1u);
        if (old == NCTA - 1) {
            g_bar_count = 0;
            __threadfence();
            atomicAdd(&g_bar_gen, 1u);
        } else {
            while (*(volatile unsigned*)&g_bar_gen == gen) { __nanosleep(32); }
        }
        __threadfence();
    }
    __syncthreads();
}

// ---- histogram helper --------------------------------------------------------
__device__ __forceinline__ void hist_add(float* h, float Iu, float Iv, float w) {
    const float LO = c_LO(), HI = c_HI(), BW = c_BW();
    if (Iu >= LO && Iu <= HI && Iv >= LO && Iv <= HI) {
        int iu = (int)floorf((Iu - LO) / BW);
        int iv = (int)floorf((Iv - LO) / BW);
        iu = min(max(iu, 0), NBINS - 1);
        iv = min(max(iv, 0), NBINS - 1);
        atomicAdd(&h[iu * NBINS + iv], w);
    }
}

// ---- FC tile -------------------------------------------------------------------
// CTA tile: NROWS neurons x KS of K. 16 warps = KG k-groups x NG n-groups.
// W tile staged in smem (coalesced once), A in registers, lane = batch.
template <int KTOT, int KS, int NROWS, int NT, int NG, int KG, int HALVES,
          bool RELU_IN, bool PACKED_A, bool ATOMIC_OUT>
__device__ __forceinline__ void fc_tile(const float* __restrict__ AT,
                                        const float* __restrict__ Wg,
                                        const float* __restrict__ bias,
                                        float* __restrict__ dest, int ldo,
                                        float* buf, int n0, int K0) {
    constexpr int CH = KS / KG;
    constexpr int NK = CH / HALVES;
    const int tid  = threadIdx.x;
    const int lane = tid & 31;
    const int w    = tid >> 5;
    const int kg   = w / NG;
    const int ng   = w % NG;

    // ---- stage W tile [NROWS x KS] into smem (each element once, coalesced)
    {
        constexpr int F4   = NROWS * KS / 4;
        constexpr int ROWF = KS / 4;
        #pragma unroll
        for (int f = tid; f < F4; f += 512) {
            int row = f / ROWF, col = f - row * ROWF;
            float4 v = *reinterpret_cast<const float4*>(
                Wg + (size_t)(n0 + row) * KTOT + K0 + col * 4);
            reinterpret_cast<float4*>(buf)[f] = v;
        }
    }
    __syncthreads();

    unsigned long long acc2[NT];
    #pragma unroll
    for (int t = 0; t < NT; ++t) acc2[t] = 0ull;

    const int kbase = K0 + kg * CH;
    const float* wrow0 = buf + (size_t)(ng * NT) * KS + kg * CH;

    #pragma unroll
    for (int h = 0; h < HALVES; ++h) {
        const int kh = kbase + h * NK;
        unsigned long long ap[NK / 2];
        if (PACKED_A) {
            const unsigned long long* src =
                reinterpret_cast<const unsigned long long*>(AT)
                + (size_t)(kh >> 1) * 32 + lane;
            #pragma unroll
            for (int j = 0; j < NK / 2; ++j) ap[j] = __ldcg(src + (size_t)j * 32);
        } else {
            #pragma unroll
            for (int j = 0; j < NK / 2; ++j) {
                float a0 = __ldcg(AT + (size_t)(kh + 2 * j) * 32 + lane);
                float a1 = __ldcg(AT + (size_t)(kh + 2 * j + 1) * 32 + lane);
                if (RELU_IN) { a0 = fmaxf(a0, 0.f); a1 = fmaxf(a1, 0.f); }
                ap[j] = pack2(a0, a1);
            }
        }
        #pragma unroll
        for (int j2 = 0; j2 < NK / 4; ++j2) {
            #pragma unroll
            for (int t = 0; t < NT; ++t) {
                ulonglong2 wv = *reinterpret_cast<const ulonglong2*>(
                    wrow0 + (size_t)t * KS + h * NK + 4 * j2);
                ffma2(acc2[t], wv.x, ap[2 * j2]);
                ffma2(acc2[t], wv.y, ap[2 * j2 + 1]);
            }
        }
    }
    __syncthreads();                        // W-tile reads done; reuse buf

    #pragma unroll
    for (int t = 0; t < NT; ++t)
        buf[(w * NT + t) * 32 + lane] = unpack_sum(acc2[t]);
    __syncthreads();

    for (int n = w; n < NROWS; n += 16) {
        const int nng = n / NT, tt = n % NT;
        float s = 0.0f;
        #pragma unroll
        for (int kk = 0; kk < KG; ++kk)
            s += buf[((kk * NG + nng) * NT + tt) * 32 + lane];
        if (ATOMIC_OUT) {
            atomicAdd(&dest[(size_t)(n0 + n) * 32 + lane], s);
        } else {
            s += __ldcg(bias + n0 + n);
            s = fmaxf(s, 0.0f);
            dest[(size_t)lane * ldo + n0 + n] = s;
        }
    }
    __syncthreads();
}

// ---- the one kernel -------------------------------------------------------------
__global__ __launch_bounds__(512, 1) void fused_kernel(
    const float* __restrict__ img,
    const float* __restrict__ W1, const float* __restrict__ b1,
    const float* __restrict__ W2, const float* __restrict__ b2,
    const float* __restrict__ W3, const float* __restrict__ b3,
    float* __restrict__ out,
    float* __restrict__ histP, float* __restrict__ x1T, float* __restrict__ x2T) {

    extern __shared__ float buf[];

    const int cta = blockIdx.x;
    const int tid = threadIdx.x;

    // ---------- Phase 0: hist (CTAs 0..31) | bias-init + W1 prefetch ----------
    if (cta < 32) {
        float* sh   = buf;                 // 3072 bins
        float* ssum = buf + 3072;
        const int b = cta;
        #pragma unroll
        for (int i = tid; i < 3072; i += 512) sh[i] = 0.0f;
        if (tid < 3) ssum[tid] = 0.0f;
        __syncthreads();

        const float* base = img + (size_t)b * 3 * 262144;
        #pragma unroll
        for (int p = tid; p < 1024; p += 512) {
            const int y = p >> 5, x = p & 31;
            const int off = (y * 16) * 512 + (x * 16);   // nearest: floor(i*16)
            float r  = base[off];
            float g  = base[262144 + off];
            float bl = base[524288 + off];
            if (r > 0.0f && g > 0.0f && bl > 0.0f) {
                float w  = sqrtf(r * r + g * g + bl * bl);
                float lr = logf(r), lg = logf(g), lb = logf(bl);
                hist_add(&sh[0],    lr - lb, lr - lg, w);
                hist_add(&sh[1024], lg - lb, lg - lr, w);
                hist_add(&sh[2048], lb - lg, lb - lr, w);
            }
        }
        __syncthreads();

        #pragma unroll
        for (int c = 0; c < 3; ++c) {
            float s = sh[c * 1024 + tid] + sh[c * 1024 + tid + 512];
            #pragma unroll
            for (int o = 16; o > 0; o >>= 1) s += __shfl_down_sync(0xffffffffu, s, o);
            if ((tid & 31) == 0) atomicAdd(&ssum[c], s);
        }
        __syncthreads();

        // pair-packed write: histP[(k/2)*64 + b*2 + (k&1)]
        #pragma unroll
        for (int i = tid; i < 1024; i += 512) {
            #pragma unroll
            for (int c = 0; c < 3; ++c) {
                const int k = c * 1024 + i;
                float v = sqrtf(sh[c * 1024 + i] / ssum[c]);
                __stcg(&histP[(k >> 1) * 64 + b * 2 + (k & 1)], v);
            }
        }
    } else {
        // 96 CTAs x 512 thr = 49152 threads: bias-init x1T/x2T, prefetch W1.
        const int idx = (cta - 32) * 512 + tid;          // 0..49151
        if (idx < 32768) __stcg(&x1T[idx], __ldcg(b1 + (idx >> 5)));
        else             { int j = idx - 32768; __stcg(&x2T[j], __ldcg(b2 + (j >> 5))); }
        const float* p0 = W1 + (size_t)idx * 64;         // two 128B lines each
        asm volatile("prefetch.global.L2 [%0];" :: "l"(p0));
        asm volatile("prefetch.global.L2 [%0];" :: "l"(p0 + 32));
    }

    grid_barrier();

    // ---------- fc1: 1024 x 3072 — 32 nb(32 n) x 4 kb(768 K) ------------------
    fc_tile<3072, 768, 32, 16, 2, 8, 2, false, true, true>(
        histP, W1, nullptr, x1T, 0, buf, (cta & 31) * 32, (cta >> 5) * 768);
    grid_barrier();

    // ---------- fc2: 512 x 1024 — 32 nb(16 n) x 4 kb(256 K), relu-in ----------
    fc_tile<1024, 256, 16, 8, 2, 8, 1, true, false, true>(
        x1T, W2, nullptr, x2T, 0, buf, (cta & 31) * 16, (cta >> 5) * 256);
    grid_barrier();

    // ---------- fc3: 256 x 512 — 2 neurons/CTA, full K, relu-in, direct out ---
    fc_tile<512, 512, 2, 2, 1, 16, 1, true, false, false>(
        x2T, W3, b3, out, 256, buf, cta * 2, 0);
}

extern "C" void kernel_launch(void* const* d_in, const int* in_sizes, int n_in,
                              void* d_out, int out_size) {
    const float* inp = (const float*)d_in[0];
    const float* W1  = (const float*)d_in[1];
    const float* b1  = (const float*)d_in[2];
    const float* W2  = (const float*)d_in[3];
    const float* b2  = (const float*)d_in[4];
    const float* W3  = (const float*)d_in[5];
    const float* b3  = (const float*)d_in[6];
    float* out = (float*)d_out;

    float* histP; cudaGetSymbolAddress((void**)&histP, g_histP);
    float* x1T;   cudaGetSymbolAddress((void**)&x1T,   g_x1T);
    float* x2T;   cudaGetSymbolAddress((void**)&x2T,   g_x2T);

    cudaFuncSetAttribute(fused_kernel,
                         cudaFuncAttributeMaxDynamicSharedMemorySize, SMEM_BYTES);
    fused_kernel<<<NCTA, 512, SMEM_BYTES>>>(inp, W1, b1, W2, b2, W3, b3, out,
                                            histP, x1T, x2T);
}

// round 7
// speedup vs baseline: 1.3395x; 1.0479x over previous
#include <cuda_runtime.h>
#include <math.h>

// ---------------------------------------------------------------------------
// SimplifiedIFEBranch — R7: persistent kernel (128 CTAs x 512 thr).
// ALL W tiles (fc1 96KB + fc2 16KB + fc3 4KB = 116KB smem) staged during the
// histogram phase (full overlap). fc phases = LDS-broadcast + FFMA2 + reduce.
// ---------------------------------------------------------------------------

#define NBINS 32
#define NCTA  128

// dynamic smem layout (floats)
#define W1_OFF 0            // 32 x 768  = 24576 floats (96 KB)
#define W2_OFF 24576        // 16 x 256  =  4096 floats (16 KB)
#define W3_OFF 28672        //  2 x 512  =  1024 floats ( 4 KB)
#define SMEM_FLOATS 29696
#define SMEM_BYTES  (SMEM_FLOATS * 4)

__device__ __forceinline__ float c_LO() { return (float)(-3.2 - (6.4 / 256.0) / 2.0); }
__device__ __forceinline__ float c_HI() { return (float)( 3.2 - (6.4 / 256.0) / 2.0); }
__device__ __forceinline__ float c_BW() {
    return (float)(((3.2 - (6.4 / 256.0) / 2.0) - (-3.2 - (6.4 / 256.0) / 2.0)) / 32.0);
}

// Scratch (__device__ globals; no allocation allowed)
__device__ float g_histP[3072 * 32];   // pair-packed: [(k/2)][b][2]
__device__ float g_x1T[1024 * 32];     // [n][b] accum, bias-preinit
__device__ float g_x2T[512 * 32];
__device__ unsigned int g_bar_count = 0;
__device__ unsigned int g_bar_gen   = 0;

// ---- packed f32x2 helpers ---------------------------------------------------
__device__ __forceinline__ unsigned long long pack2(float x, float y) {
    unsigned long long r;
    asm("mov.b64 %0, {%1, %2};" : "=l"(r) : "f"(x), "f"(y));
    return r;
}
__device__ __forceinline__ void ffma2(unsigned long long& d,
                                      unsigned long long a, unsigned long long b) {
    asm("fma.rn.f32x2 %0, %1, %2, %0;" : "+l"(d) : "l"(a), "l"(b));
}
__device__ __forceinline__ float unpack_sum(unsigned long long p) {
    float lo, hi;
    asm("mov.b64 {%0, %1}, %2;" : "=f"(lo), "=f"(hi) : "l"(p));
    return lo + hi;
}

// ---- software grid barrier ----------------------------------------------------
__device__ __forceinline__ void grid_barrier() {
    __syncthreads();
    if (threadIdx.x == 0) {
        unsigned gen = *(volatile unsigned*)&g_bar_gen;
        __threadfence();
        unsigned old = atomicAdd(&g_bar_count, 1u);
        if (old == NCTA - 1) {
            g_bar_count = 0;
            __threadfence();
            atomicAdd(&g_bar_gen, 1u);
        } else {
            while (*(volatile unsigned*)&g_bar_gen == gen) { __nanosleep(32); }
        }
        __threadfence();
    }
    __syncthreads();
}

// ---- histogram helper -----------------------------------------------------------
__device__ __forceinline__ void hist_add(float* h, float Iu, float Iv, float w) {
    const float LO = c_LO(), HI = c_HI(), BW = c_BW();
    if (Iu >= LO && Iu <= HI && Iv >= LO && Iv <= HI) {
        int iu = (int)floorf((Iu - LO) / BW);
        int iv = (int)floorf((Iv - LO) / BW);
        iu = min(max(iu, 0), NBINS - 1);
        iv = min(max(iv, 0), NBINS - 1);
        atomicAdd(&h[iu * NBINS + iv], w);
    }
}

// ---- coalesced W tile stage (global -> smem), each element once ----------------
template <int ROWS, int COLS>
__device__ __forceinline__ void stage_tile(float* dst, const float* src, int ld) {
    constexpr int F4 = ROWS * COLS / 4;
    constexpr int RF = COLS / 4;
    #pragma unroll
    for (int f = threadIdx.x; f < F4; f += 512) {
        const int row = f / RF, col = f - row * RF;
        float4 v = __ldcg(reinterpret_cast<const float4*>(src + (size_t)row * ld + col * 4));
        reinterpret_cast<float4*>(dst)[f] = v;
    }
}

// ---- FC compute (W tile already in smem) ----------------------------------------
// 16 warps = KG k-groups x NG n-groups; NT neurons per warp; lane = batch.
template <int KS, int NROWS, int NT, int NG, int KG, int HALVES,
          bool RELU_IN, bool PACKED_A, bool ATOMIC_OUT>
__device__ __forceinline__ void fc_compute(const float* __restrict__ AT,
                                           const float* wtile,
                                           const float* __restrict__ bias,
                                           float* __restrict__ dest, int ldo,
                                           float* scratch, int n0, int K0) {
    constexpr int CH = KS / KG;
    constexpr int NK = CH / HALVES;
    const int tid  = threadIdx.x;
    const int lane = tid & 31;
    const int w    = tid >> 5;
    const int kg   = w / NG;
    const int ng   = w % NG;

    unsigned long long acc2[NT];
    #pragma unroll
    for (int t = 0; t < NT; ++t) acc2[t] = 0ull;

    const int kbase = K0 + kg * CH;
    const float* wrow0 = wtile + (size_t)(ng * NT) * KS + kg * CH;

    #pragma unroll
    for (int h = 0; h < HALVES; ++h) {
        const int kh = kbase + h * NK;
        unsigned long long ap[NK / 2];
        if (PACKED_A) {
            const unsigned long long* src =
                reinterpret_cast<const unsigned long long*>(AT)
                + (size_t)(kh >> 1) * 32 + lane;
            #pragma unroll
            for (int j = 0; j < NK / 2; ++j) ap[j] = __ldcg(src + (size_t)j * 32);
        } else {
            #pragma unroll
            for (int j = 0; j < NK / 2; ++j) {
                float a0 = __ldcg(AT + (size_t)(kh + 2 * j) * 32 + lane);
                float a1 = __ldcg(AT + (size_t)(kh + 2 * j + 1) * 32 + lane);
                if (RELU_IN) { a0 = fmaxf(a0, 0.f); a1 = fmaxf(a1, 0.f); }
                ap[j] = pack2(a0, a1);
            }
        }
        #pragma unroll
        for (int j2 = 0; j2 < NK / 4; ++j2) {
            #pragma unroll
            for (int t = 0; t < NT; ++t) {
                ulonglong2 wv = *reinterpret_cast<const ulonglong2*>(
                    wrow0 + (size_t)t * KS + h * NK + 4 * j2);
                ffma2(acc2[t], wv.x, ap[2 * j2]);
                ffma2(acc2[t], wv.y, ap[2 * j2 + 1]);
            }
        }
    }
    __syncthreads();                        // wtile reads done; scratch may alias

    #pragma unroll
    for (int t = 0; t < NT; ++t)
        scratch[(w * NT + t) * 32 + lane] = unpack_sum(acc2[t]);
    __syncthreads();

    for (int n = w; n < NROWS; n += 16) {
        const int nng = n / NT, tt = n % NT;
        float s = 0.0f;
        #pragma unroll
        for (int kk = 0; kk < KG; ++kk)
            s += scratch[((kk * NG + nng) * NT + tt) * 32 + lane];
        if (ATOMIC_OUT) {
            atomicAdd(&dest[(size_t)(n0 + n) * 32 + lane], s);
        } else {
            s += __ldcg(bias + n0 + n);
            s = fmaxf(s, 0.0f);
            dest[(size_t)lane * ldo + n0 + n] = s;
        }
    }
    __syncthreads();
}

// ---- the one kernel ----------------------------------------------------------------
__global__ __launch_bounds__(512, 1) void fused_kernel(
    const float* __restrict__ img,
    const float* __restrict__ W1, const float* __restrict__ b1,
    const float* __restrict__ W2, const float* __restrict__ b2,
    const float* __restrict__ W3, const float* __restrict__ b3,
    float* __restrict__ out,
    float* __restrict__ histP, float* __restrict__ x1T, float* __restrict__ x2T) {

    extern __shared__ float buf[];          // W tiles + reduce scratch
    __shared__ float sh[3 * 1024];          // hist bins (static, coexists)
    __shared__ float ssum[3];

    const int cta = blockIdx.x;
    const int tid = threadIdx.x;

    // =========== Phase 0: stage ALL W tiles + bias init + hist (overlapped) =====
    // W tiles for this CTA's fc1/fc2/fc3 assignments:
    stage_tile<32, 768>(buf + W1_OFF,
                        W1 + (size_t)((cta & 31) * 32) * 3072 + (cta >> 5) * 768, 3072);
    stage_tile<16, 256>(buf + W2_OFF,
                        W2 + (size_t)((cta & 31) * 16) * 1024 + (cta >> 5) * 256, 1024);
    stage_tile<2, 512>(buf + W3_OFF, W3 + (size_t)(cta * 2) * 512, 512);

    // bias pre-init of accumulators, spread over all 65536 threads
    {
        const int idx = cta * 512 + tid;                 // 0..65535
        if (idx < 32768)       __stcg(&x1T[idx], __ldcg(b1 + (idx >> 5)));
        else if (idx < 49152)  { int j = idx - 32768; __stcg(&x2T[j], __ldcg(b2 + (j >> 5))); }
    }

    if (cta < 32) {
        const int b = cta;
        #pragma unroll
        for (int i = tid; i < 3072; i += 512) sh[i] = 0.0f;
        if (tid < 3) ssum[tid] = 0.0f;
        __syncthreads();

        // two pixels per thread, all 6 loads batched up front
        const float* base = img + (size_t)b * 3 * 262144;
        const int p0 = tid, p1 = tid + 512;
        const int off0 = ((p0 >> 5) * 16) * 512 + ((p0 & 31) * 16);
        const int off1 = ((p1 >> 5) * 16) * 512 + ((p1 & 31) * 16);
        float r0 = __ldcg(base + off0);
        float g0 = __ldcg(base + 262144 + off0);
        float l0 = __ldcg(base + 524288 + off0);
        float r1 = __ldcg(base + off1);
        float g1 = __ldcg(base + 262144 + off1);
        float l1 = __ldcg(base + 524288 + off1);

        if (r0 > 0.0f && g0 > 0.0f && l0 > 0.0f) {
            float w  = sqrtf(r0 * r0 + g0 * g0 + l0 * l0);
            float lr = logf(r0), lg = logf(g0), lb = logf(l0);
            hist_add(&sh[0],    lr - lb, lr - lg, w);
            hist_add(&sh[1024], lg - lb, lg - lr, w);
            hist_add(&sh[2048], lb - lg, lb - lr, w);
        }
        if (r1 > 0.0f && g1 > 0.0f && l1 > 0.0f) {
            float w  = sqrtf(r1 * r1 + g1 * g1 + l1 * l1);
            float lr = logf(r1), lg = logf(g1), lb = logf(l1);
            hist_add(&sh[0],    lr - lb, lr - lg, w);
            hist_add(&sh[1024], lg - lb, lg - lr, w);
            hist_add(&sh[2048], lb - lg, lb - lr, w);
        }
        __syncthreads();

        #pragma unroll
        for (int c = 0; c < 3; ++c) {
            float s = sh[c * 1024 + tid] + sh[c * 1024 + tid + 512];
            #pragma unroll
            for (int o = 16; o > 0; o >>= 1) s += __shfl_down_sync(0xffffffffu, s, o);
            if ((tid & 31) == 0) atomicAdd(&ssum[c], s);
        }
        __syncthreads();

        // pair-packed write: histP[(k/2)*64 + b*2 + (k&1)]
        #pragma unroll
        for (int i = tid; i < 1024; i += 512) {
            #pragma unroll
            for (int c = 0; c < 3; ++c) {
                const int k = c * 1024 + i;
                float v = sqrtf(sh[c * 1024 + i] / ssum[c]);
                __stcg(&histP[(k >> 1) * 64 + b * 2 + (k & 1)], v);
            }
        }
    }

    grid_barrier();

    // =========== fc1: 1024 x 3072 — 32 nb(32 n) x 4 kb(768 K) ==================
    fc_compute<768, 32, 16, 2, 8, 2, false, true, true>(
        histP, buf + W1_OFF, nullptr, x1T, 0, buf, (cta & 31) * 32, (cta >> 5) * 768);
    grid_barrier();

    // =========== fc2: 512 x 1024 — 32 nb(16 n) x 4 kb(256 K), relu-in ==========
    fc_compute<256, 16, 8, 2, 8, 1, true, false, true>(
        x1T, buf + W2_OFF, nullptr, x2T, 0, buf, (cta & 31) * 16, (cta >> 5) * 256);
    grid_barrier();

    // =========== fc3: 256 x 512 — 2 neurons/CTA, full K, relu-in, direct out ====
    fc_compute<512, 2, 2, 1, 16, 1, true, false, false>(
        x2T, buf + W3_OFF, b3, out, 256, buf, cta * 2, 0);
}

extern "C" void kernel_launch(void* const* d_in, const int* in_sizes, int n_in,
                              void* d_out, int out_size) {
    const float* inp = (const float*)d_in[0];
    const float* W1  = (const float*)d_in[1];
    const float* b1  = (const float*)d_in[2];
    const float* W2  = (const float*)d_in[3];
    const float* b2  = (const float*)d_in[4];
    const float* W3  = (const float*)d_in[5];
    const float* b3  = (const float*)d_in[6];
    float* out = (float*)d_out;

    float* histP; cudaGetSymbolAddress((void**)&histP, g_histP);
    float* x1T;   cudaGetSymbolAddress((void**)&x1T,   g_x1T);
    float* x2T;   cudaGetSymbolAddress((void**)&x2T,   g_x2T);

    cudaFuncSetAttribute(fused_kernel,
                         cudaFuncAttributeMaxDynamicSharedMemorySize, SMEM_BYTES);
    fused_kernel<<<NCTA, 512, SMEM_BYTES>>>(inp, W1, b1, W2, b2, W3, b3, out,
                                            histP, x1T, x2T);
}